// round 2
// baseline (speedup 1.0000x reference)
#include <cuda_runtime.h>

// Problem constants (fixed shapes from setup_inputs)
#define HH      96
#define WW      96
#define NPTS    9216          // H*W
#define BATCH   2
#define CH      21
#define RECF    32            // floats per packed point record (128 B)
#define MSPLIT  4             // m-range split for grid parallelism
#define CHUNK   (NPTS / MSPLIT)   // 2304
#define NTILES  18            // n tiles per batch (9216 / 512)
#define TPB     256
#define RPT     2             // n-points per thread
#define PSTRIDE 24            // floats per point in partial buffer (16B-aligned stride)

// Record layout (32 floats = 128 B, 16B aligned):
//   [0..4]  g = feature * sqrt(log2 e)   (2 spatial + 3 color)
//   [5]     c = -0.5 * ||g||^2
//   [6..7]  pad (0)
//   [8..28] vals v0..v20 (cur_state channels)
//   [29..31] pad (0)   -> channel pair 10 covers (v20, 0)
__device__ __align__(16) float g_recs[BATCH * NPTS * RECF];
__device__ __align__(16) float g_partial[MSPLIT * BATCH * NPTS * PSTRIDE];

__device__ __forceinline__ float ex2f(float x) {
    float y;
    asm("ex2.approx.f32 %0, %1;" : "=f"(y) : "f"(x));
    return y;
}

__device__ __forceinline__ unsigned long long pack2(float a) {
    unsigned long long r;
    unsigned int u = __float_as_uint(a);
    asm("mov.b64 %0, {%1, %1};" : "=l"(r) : "r"(u));
    return r;
}

__device__ __forceinline__ unsigned long long fma2(unsigned long long a,
                                                   unsigned long long b,
                                                   unsigned long long c) {
    unsigned long long d;
    asm("fma.rn.f32x2 %0, %1, %2, %3;" : "=l"(d) : "l"(a), "l"(b), "l"(c));
    return d;
}

// ---------------------------------------------------------------------------
// Pass 1: build packed point records (features in log2 domain + values)
// ---------------------------------------------------------------------------
__global__ void prep_kernel(const float* __restrict__ cur_state,
                            const float* __restrict__ img) {
    int idx = blockIdx.x * blockDim.x + threadIdx.x;
    if (idx >= BATCH * NPTS) return;
    int b = idx / NPTS;
    int n = idx - b * NPTS;
    int y = n / WW;
    int x = n - y * WW;

    const float S = 1.2011224087864498f;   // sqrt(log2(e))
    float g0 = (float)y * (S / 8.0f);      // / THETA_ALPHA
    float g1 = (float)x * (S / 8.0f);
    float g2 = img[(b * 3 + 0) * NPTS + n] * (S * 2.0f);  // / THETA_BETA
    float g3 = img[(b * 3 + 1) * NPTS + n] * (S * 2.0f);
    float g4 = img[(b * 3 + 2) * NPTS + n] * (S * 2.0f);
    float c = -0.5f * (g0 * g0 + g1 * g1 + g2 * g2 + g3 * g3 + g4 * g4);

    float* r = g_recs + (size_t)idx * RECF;
    r[0] = g0; r[1] = g1; r[2] = g2; r[3] = g3; r[4] = g4;
    r[5] = c;  r[6] = 0.0f; r[7] = 0.0f;
#pragma unroll
    for (int cc = 0; cc < CH; cc++)
        r[8 + cc] = cur_state[(b * CH + cc) * NPTS + n];
    r[29] = 0.0f; r[30] = 0.0f; r[31] = 0.0f;
}

// ---------------------------------------------------------------------------
// Pass 2: main pair loop. Each thread owns RPT consecutive n-points, iterates
// one m-chunk. All lanes in a warp read the SAME m-record (broadcast LDG).
// K(n,m) = ex2(g_n.g_m + c_n + c_m); out accumulated as 11 packed f32x2.
// ---------------------------------------------------------------------------
__global__ __launch_bounds__(TPB) void gauss_kernel() {
    int s  = blockIdx.x;              // m-split
    int nt = blockIdx.y;              // n tile
    int b  = blockIdx.z;              // batch
    int t  = threadIdx.x;
    int n0 = nt * (TPB * RPT) + t * RPT;

    const float* recs = g_recs + (size_t)b * NPTS * RECF;

    float gn[RPT][5], cn[RPT];
#pragma unroll
    for (int r = 0; r < RPT; r++) {
        const float* rn = recs + (size_t)(n0 + r) * RECF;
        gn[r][0] = rn[0]; gn[r][1] = rn[1]; gn[r][2] = rn[2];
        gn[r][3] = rn[3]; gn[r][4] = rn[4];
        cn[r] = rn[5];
    }

    unsigned long long acc[RPT][11];
#pragma unroll
    for (int r = 0; r < RPT; r++)
#pragma unroll
        for (int j = 0; j < 11; j++)
            acc[r][j] = 0ull;

    int m0 = s * CHUNK;
#pragma unroll 2
    for (int mm = 0; mm < CHUNK; mm++) {
        const float* rmbase = recs + (size_t)(m0 + mm) * RECF;
        const float4* rm = (const float4*)rmbase;
        float4 a = rm[0];                  // g0..g3
        float4 e = rm[1];                  // g4, c_m, pad, pad
        const ulonglong2* rv = (const ulonglong2*)(rmbase + 8);
        ulonglong2 v0 = rv[0];
        ulonglong2 v1 = rv[1];
        ulonglong2 v2 = rv[2];
        ulonglong2 v3 = rv[3];
        ulonglong2 v4 = rv[4];
        ulonglong2 v5 = rv[5];

#pragma unroll
        for (int r = 0; r < RPT; r++) {
            float arg = cn[r] + e.y;
            arg = fmaf(gn[r][0], a.x, arg);
            arg = fmaf(gn[r][1], a.y, arg);
            arg = fmaf(gn[r][2], a.z, arg);
            arg = fmaf(gn[r][3], a.w, arg);
            arg = fmaf(gn[r][4], e.x, arg);
            unsigned long long kk = pack2(ex2f(arg));
            acc[r][0]  = fma2(kk, v0.x, acc[r][0]);
            acc[r][1]  = fma2(kk, v0.y, acc[r][1]);
            acc[r][2]  = fma2(kk, v1.x, acc[r][2]);
            acc[r][3]  = fma2(kk, v1.y, acc[r][3]);
            acc[r][4]  = fma2(kk, v2.x, acc[r][4]);
            acc[r][5]  = fma2(kk, v2.y, acc[r][5]);
            acc[r][6]  = fma2(kk, v3.x, acc[r][6]);
            acc[r][7]  = fma2(kk, v3.y, acc[r][7]);
            acc[r][8]  = fma2(kk, v4.x, acc[r][8]);
            acc[r][9]  = fma2(kk, v4.y, acc[r][9]);
            acc[r][10] = fma2(kk, v5.x, acc[r][10]);
        }
    }

#pragma unroll
    for (int r = 0; r < RPT; r++) {
        unsigned long long* p = (unsigned long long*)
            (g_partial + (size_t)(((s * BATCH + b) * NPTS) + (n0 + r)) * PSTRIDE);
#pragma unroll
        for (int j = 0; j < 11; j++)
            p[j] = acc[r][j];
    }
}

// ---------------------------------------------------------------------------
// Pass 3: deterministic reduction over the MSPLIT partials, with transpose
// to the [b][c][n] output layout.
// ---------------------------------------------------------------------------
__global__ void reduce_kernel(float* __restrict__ out) {
    int idx = blockIdx.x * blockDim.x + threadIdx.x;
    if (idx >= BATCH * CH * NPTS) return;
    int n = idx % NPTS;
    int c = (idx / NPTS) % CH;
    int b = idx / (NPTS * CH);
    float sum = 0.0f;
#pragma unroll
    for (int s = 0; s < MSPLIT; s++)
        sum += g_partial[(size_t)(((s * BATCH + b) * NPTS) + n) * PSTRIDE + c];
    out[idx] = sum;
}

extern "C" void kernel_launch(void* const* d_in, const int* in_sizes, int n_in,
                              void* d_out, int out_size) {
    const float* cur_state = (const float*)d_in[0];   // [2,21,96,96]
    const float* img       = (const float*)d_in[1];   // [2,3,96,96]
    float* out             = (float*)d_out;           // [2,21,96,96]

    prep_kernel<<<(BATCH * NPTS + 255) / 256, 256>>>(cur_state, img);
    gauss_kernel<<<dim3(MSPLIT, NTILES, BATCH), TPB>>>();
    reduce_kernel<<<(BATCH * CH * NPTS + 255) / 256, 256>>>(out);
}

// round 3
// speedup vs baseline: 3.7820x; 3.7820x over previous
#include <cuda_runtime.h>
#include <cstdint>

// Fixed problem shapes
#define NPTS    9216           // 96*96
#define WW      96
#define BATCH   2
#define CH      21
#define RECF    32             // floats per packed record (128 B)
#define MSPLIT  8              // m-range splits
#define CHUNK   (NPTS / MSPLIT)    // 1152
#define TPB     256
#define RPT     4              // n-points per thread
#define NTILE   (TPB * RPT)        // 1024
#define NTILES  (NPTS / NTILE)     // 9
#define TM      96             // m-records per smem stage (12 KB)
#define NSTAGES (CHUNK / TM)       // 12
#define PSTRIDE 24             // floats per point in partial buffer

// Record layout (32 floats = 128 B):
//  [0..4] g = feat * sqrt(log2 e)   [5] c = -0.5*||g||^2   [6..7] pad
//  [8..28] v0..v20                  [29..31] pad (zeros)
__device__ __align__(16) float g_recs[BATCH * NPTS * RECF];
__device__ __align__(16) float g_partial[MSPLIT * BATCH * NPTS * PSTRIDE];

// ---------------- helpers ----------------
__device__ __forceinline__ float ex2f(float x) {
    float y; asm("ex2.approx.f32 %0, %1;" : "=f"(y) : "f"(x)); return y;
}
__device__ __forceinline__ unsigned long long pack2(float a) {
    unsigned long long r; unsigned u = __float_as_uint(a);
    asm("mov.b64 %0, {%1, %1};" : "=l"(r) : "r"(u)); return r;
}
__device__ __forceinline__ unsigned long long packab(float a, float b) {
    unsigned long long r;
    asm("mov.b64 %0, {%1, %2};" : "=l"(r) : "r"(__float_as_uint(a)), "r"(__float_as_uint(b)));
    return r;
}
__device__ __forceinline__ void unpack2(unsigned long long p, float& a, float& b) {
    unsigned x, y;
    asm("mov.b64 {%0, %1}, %2;" : "=r"(x), "=r"(y) : "l"(p));
    a = __uint_as_float(x); b = __uint_as_float(y);
}
__device__ __forceinline__ unsigned long long fma2(unsigned long long a,
                                                   unsigned long long b,
                                                   unsigned long long c) {
    unsigned long long d;
    asm("fma.rn.f32x2 %0, %1, %2, %3;" : "=l"(d) : "l"(a), "l"(b), "l"(c));
    return d;
}
__device__ __forceinline__ unsigned long long add2(unsigned long long a,
                                                   unsigned long long b) {
    unsigned long long d;
    asm("add.rn.f32x2 %0, %1, %2;" : "=l"(d) : "l"(a), "l"(b));
    return d;
}
__device__ __forceinline__ void cp_async16(uint32_t saddr, const void* gaddr) {
    asm volatile("cp.async.cg.shared.global [%0], [%1], 16;" :: "r"(saddr), "l"(gaddr));
}
__device__ __forceinline__ void cp_commit() {
    asm volatile("cp.async.commit_group;" ::: "memory");
}
template <int N>
__device__ __forceinline__ void cp_wait() {
    asm volatile("cp.async.wait_group %0;" :: "n"(N) : "memory");
}

// ---------------------------------------------------------------------------
// Pass 1: build packed records (features in log2 domain + channel values)
// ---------------------------------------------------------------------------
__global__ void prep_kernel(const float* __restrict__ cur_state,
                            const float* __restrict__ img) {
    int idx = blockIdx.x * blockDim.x + threadIdx.x;
    if (idx >= BATCH * NPTS) return;
    int b = idx / NPTS;
    int n = idx - b * NPTS;
    int y = n / WW;
    int x = n - y * WW;

    const float S = 1.2011224087864498f;   // sqrt(log2 e)
    float g0 = (float)y * (S / 8.0f);
    float g1 = (float)x * (S / 8.0f);
    float g2 = img[(b * 3 + 0) * NPTS + n] * (S * 2.0f);
    float g3 = img[(b * 3 + 1) * NPTS + n] * (S * 2.0f);
    float g4 = img[(b * 3 + 2) * NPTS + n] * (S * 2.0f);
    float c = -0.5f * (g0 * g0 + g1 * g1 + g2 * g2 + g3 * g3 + g4 * g4);

    float* r = g_recs + (size_t)idx * RECF;
    r[0] = g0; r[1] = g1; r[2] = g2; r[3] = g3; r[4] = g4;
    r[5] = c;  r[6] = 0.0f; r[7] = 0.0f;
#pragma unroll
    for (int cc = 0; cc < CH; cc++)
        r[8 + cc] = cur_state[(b * CH + cc) * NPTS + n];
    r[29] = 0.0f; r[30] = 0.0f; r[31] = 0.0f;
}

// ---------------------------------------------------------------------------
// Pass 2: pair loop. cp.async double-buffered smem staging of m-records;
// each thread owns 4 consecutive n-points; args computed as f32x2 pairs.
// ---------------------------------------------------------------------------
__global__ __launch_bounds__(TPB) void gauss_kernel() {
    __shared__ __align__(16) float smbuf[2][TM * RECF];   // 2 x 12 KB

    int s  = blockIdx.x;          // m-split
    int nt = blockIdx.y;          // n tile
    int b  = blockIdx.z;          // batch
    int t  = threadIdx.x;
    int n0 = nt * NTILE + t * RPT;

    const float* recs = g_recs + (size_t)b * NPTS * RECF;

    // Per-thread n features, packed as pairs (r0,r1) and (r2,r3)
    float4 A[RPT], E[RPT];
#pragma unroll
    for (int r = 0; r < RPT; r++) {
        const float4* rn = (const float4*)(recs + (size_t)(n0 + r) * RECF);
        A[r] = rn[0];  // g0..g3
        E[r] = rn[1];  // g4, c, pad, pad
    }
    unsigned long long gp[2][5], cpn[2];
#pragma unroll
    for (int r2 = 0; r2 < 2; r2++) {
        gp[r2][0] = packab(A[2 * r2].x, A[2 * r2 + 1].x);
        gp[r2][1] = packab(A[2 * r2].y, A[2 * r2 + 1].y);
        gp[r2][2] = packab(A[2 * r2].z, A[2 * r2 + 1].z);
        gp[r2][3] = packab(A[2 * r2].w, A[2 * r2 + 1].w);
        gp[r2][4] = packab(E[2 * r2].x, E[2 * r2 + 1].x);
        cpn[r2]   = packab(E[2 * r2].y, E[2 * r2 + 1].y);
    }

    unsigned long long acc[RPT][11];
#pragma unroll
    for (int r = 0; r < RPT; r++)
#pragma unroll
        for (int j = 0; j < 11; j++)
            acc[r][j] = 0ull;

    const float* gsrc = recs + (size_t)s * CHUNK * RECF;

    // prologue: stage 0 -> buf 0
    {
        uint32_t sb = (uint32_t)__cvta_generic_to_shared(&smbuf[0][0]);
#pragma unroll
        for (int k = 0; k < 3; k++) {
            int ci = t + k * TPB;                // 0..767 16B-chunks
            cp_async16(sb + ci * 16, gsrc + ci * 4);
        }
        cp_commit();
    }

    for (int st = 0; st < NSTAGES; st++) {
        __syncthreads();   // buffer (st+1)&1 no longer being read
        if (st + 1 < NSTAGES) {
            uint32_t sb = (uint32_t)__cvta_generic_to_shared(&smbuf[(st + 1) & 1][0]);
            const float* base = gsrc + (size_t)(st + 1) * TM * RECF;
#pragma unroll
            for (int k = 0; k < 3; k++) {
                int ci = t + k * TPB;
                cp_async16(sb + ci * 16, base + ci * 4);
            }
            cp_commit();
            cp_wait<1>();      // stage st complete (groups finish in order)
        } else {
            cp_wait<0>();
        }
        __syncthreads();

        const float* buf = &smbuf[st & 1][0];
#pragma unroll 1
        for (int mm = 0; mm < TM; mm++) {
            const float4* rp = (const float4*)(buf + mm * RECF);
            float4 a = rp[0];
            float4 e = rp[1];
            const ulonglong2* rv = (const ulonglong2*)(rp + 2);
            ulonglong2 v0 = rv[0];
            ulonglong2 v1 = rv[1];
            ulonglong2 v2 = rv[2];
            ulonglong2 v3 = rv[3];
            ulonglong2 v4 = rv[4];
            ulonglong2 v5 = rv[5];

            unsigned long long cm2 = pack2(e.y);
            unsigned long long g0m = pack2(a.x);
            unsigned long long g1m = pack2(a.y);
            unsigned long long g2m = pack2(a.z);
            unsigned long long g3m = pack2(a.w);
            unsigned long long g4m = pack2(e.x);

#pragma unroll
            for (int r2 = 0; r2 < 2; r2++) {
                unsigned long long arg = add2(cpn[r2], cm2);
                arg = fma2(gp[r2][0], g0m, arg);
                arg = fma2(gp[r2][1], g1m, arg);
                arg = fma2(gp[r2][2], g2m, arg);
                arg = fma2(gp[r2][3], g3m, arg);
                arg = fma2(gp[r2][4], g4m, arg);
                float a0, a1;
                unpack2(arg, a0, a1);
                unsigned long long k0 = pack2(ex2f(a0));
                unsigned long long k1 = pack2(ex2f(a1));
                int r = 2 * r2;
                acc[r][0]  = fma2(k0, v0.x, acc[r][0]);
                acc[r][1]  = fma2(k0, v0.y, acc[r][1]);
                acc[r][2]  = fma2(k0, v1.x, acc[r][2]);
                acc[r][3]  = fma2(k0, v1.y, acc[r][3]);
                acc[r][4]  = fma2(k0, v2.x, acc[r][4]);
                acc[r][5]  = fma2(k0, v2.y, acc[r][5]);
                acc[r][6]  = fma2(k0, v3.x, acc[r][6]);
                acc[r][7]  = fma2(k0, v3.y, acc[r][7]);
                acc[r][8]  = fma2(k0, v4.x, acc[r][8]);
                acc[r][9]  = fma2(k0, v4.y, acc[r][9]);
                acc[r][10] = fma2(k0, v5.x, acc[r][10]);
                r = 2 * r2 + 1;
                acc[r][0]  = fma2(k1, v0.x, acc[r][0]);
                acc[r][1]  = fma2(k1, v0.y, acc[r][1]);
                acc[r][2]  = fma2(k1, v1.x, acc[r][2]);
                acc[r][3]  = fma2(k1, v1.y, acc[r][3]);
                acc[r][4]  = fma2(k1, v2.x, acc[r][4]);
                acc[r][5]  = fma2(k1, v2.y, acc[r][5]);
                acc[r][6]  = fma2(k1, v3.x, acc[r][6]);
                acc[r][7]  = fma2(k1, v3.y, acc[r][7]);
                acc[r][8]  = fma2(k1, v4.x, acc[r][8]);
                acc[r][9]  = fma2(k1, v4.y, acc[r][9]);
                acc[r][10] = fma2(k1, v5.x, acc[r][10]);
            }
        }
    }

#pragma unroll
    for (int r = 0; r < RPT; r++) {
        unsigned long long* p = (unsigned long long*)
            (g_partial + (size_t)(((s * BATCH + b) * NPTS) + (n0 + r)) * PSTRIDE);
#pragma unroll
        for (int j = 0; j < 11; j++)
            p[j] = acc[r][j];
    }
}

// ---------------------------------------------------------------------------
// Pass 3: deterministic reduction over MSPLIT partials (+ transpose)
// ---------------------------------------------------------------------------
__global__ void reduce_kernel(float* __restrict__ out) {
    int idx = blockIdx.x * blockDim.x + threadIdx.x;
    if (idx >= BATCH * CH * NPTS) return;
    int n = idx % NPTS;
    int c = (idx / NPTS) % CH;
    int b = idx / (NPTS * CH);
    float sum = 0.0f;
#pragma unroll
    for (int s = 0; s < MSPLIT; s++)
        sum += g_partial[(size_t)(((s * BATCH + b) * NPTS) + n) * PSTRIDE + c];
    out[idx] = sum;
}

extern "C" void kernel_launch(void* const* d_in, const int* in_sizes, int n_in,
                              void* d_out, int out_size) {
    const float* cur_state = (const float*)d_in[0];   // [2,21,96,96]
    const float* img       = (const float*)d_in[1];   // [2,3,96,96]
    float* out             = (float*)d_out;           // [2,21,96,96]

    prep_kernel<<<(BATCH * NPTS + 255) / 256, 256>>>(cur_state, img);
    gauss_kernel<<<dim3(MSPLIT, NTILES, BATCH), TPB>>>();
    reduce_kernel<<<(BATCH * CH * NPTS + 255) / 256, 256>>>(out);
}

// round 4
// speedup vs baseline: 3.9750x; 1.0510x over previous
#include <cuda_runtime.h>
#include <cstdint>

// Fixed problem shapes
#define NPTS    9216           // 96*96
#define WW      96
#define BATCH   2
#define CH      21
#define RECF    32             // floats per packed record (128 B)
#define MSPLIT  8              // m-range splits
#define CHUNK   (NPTS / MSPLIT)    // 1152
#define TPB     256
#define RPT     4              // n-points per thread
#define NTILE   (TPB * RPT)        // 1024
#define NTILES  (NPTS / NTILE)     // 9
#define TM      96             // m-records per smem stage (12 KB)
#define NSTAGES (CHUNK / TM)       // 12
#define PSTRIDE 24             // floats per point in partial buffer

// Record layout (32 floats = 128 B):
//  [0..4] g = feat * sqrt(log2 e)   [5] c = -0.5*||g||^2   [6..7] pad
//  [8..28] v0..v20                  [29..31] pad (zeros)
__device__ __align__(16) float g_recs[BATCH * NPTS * RECF];
__device__ __align__(16) float g_partial[MSPLIT * BATCH * NPTS * PSTRIDE];

// ---------------- helpers ----------------
__device__ __forceinline__ float ex2f(float x) {
    float y; asm("ex2.approx.f32 %0, %1;" : "=f"(y) : "f"(x)); return y;
}
__device__ __forceinline__ unsigned long long pack2(float a) {
    unsigned long long r; unsigned u = __float_as_uint(a);
    asm("mov.b64 %0, {%1, %1};" : "=l"(r) : "r"(u)); return r;
}
__device__ __forceinline__ unsigned long long packab(float a, float b) {
    unsigned long long r;
    asm("mov.b64 %0, {%1, %2};" : "=l"(r) : "r"(__float_as_uint(a)), "r"(__float_as_uint(b)));
    return r;
}
__device__ __forceinline__ void unpack2(unsigned long long p, float& a, float& b) {
    unsigned x, y;
    asm("mov.b64 {%0, %1}, %2;" : "=r"(x), "=r"(y) : "l"(p));
    a = __uint_as_float(x); b = __uint_as_float(y);
}
__device__ __forceinline__ unsigned long long fma2(unsigned long long a,
                                                   unsigned long long b,
                                                   unsigned long long c) {
    unsigned long long d;
    asm("fma.rn.f32x2 %0, %1, %2, %3;" : "=l"(d) : "l"(a), "l"(b), "l"(c));
    return d;
}
__device__ __forceinline__ unsigned long long add2(unsigned long long a,
                                                   unsigned long long b) {
    unsigned long long d;
    asm("add.rn.f32x2 %0, %1, %2;" : "=l"(d) : "l"(a), "l"(b));
    return d;
}
__device__ __forceinline__ void cp_async16(uint32_t saddr, const void* gaddr) {
    asm volatile("cp.async.cg.shared.global [%0], [%1], 16;" :: "r"(saddr), "l"(gaddr));
}
__device__ __forceinline__ void cp_commit() {
    asm volatile("cp.async.commit_group;" ::: "memory");
}
template <int N>
__device__ __forceinline__ void cp_wait() {
    asm volatile("cp.async.wait_group %0;" :: "n"(N) : "memory");
}

// ---------------------------------------------------------------------------
// Pass 1: build packed records (features in log2 domain + channel values)
// ---------------------------------------------------------------------------
__global__ void prep_kernel(const float* __restrict__ cur_state,
                            const float* __restrict__ img) {
    int idx = blockIdx.x * blockDim.x + threadIdx.x;
    if (idx >= BATCH * NPTS) return;
    int b = idx / NPTS;
    int n = idx - b * NPTS;
    int y = n / WW;
    int x = n - y * WW;

    const float S = 1.2011224087864498f;   // sqrt(log2 e)
    float g0 = (float)y * (S / 8.0f);
    float g1 = (float)x * (S / 8.0f);
    float g2 = img[(b * 3 + 0) * NPTS + n] * (S * 2.0f);
    float g3 = img[(b * 3 + 1) * NPTS + n] * (S * 2.0f);
    float g4 = img[(b * 3 + 2) * NPTS + n] * (S * 2.0f);
    float c = -0.5f * (g0 * g0 + g1 * g1 + g2 * g2 + g3 * g3 + g4 * g4);

    float* r = g_recs + (size_t)idx * RECF;
    r[0] = g0; r[1] = g1; r[2] = g2; r[3] = g3; r[4] = g4;
    r[5] = c;  r[6] = 0.0f; r[7] = 0.0f;
#pragma unroll
    for (int cc = 0; cc < CH; cc++)
        r[8 + cc] = cur_state[(b * CH + cc) * NPTS + n];
    r[29] = 0.0f; r[30] = 0.0f; r[31] = 0.0f;
}

// ---------------------------------------------------------------------------
// Pass 2: pair loop. cp.async double-buffered smem staging of m-records;
// each thread owns 4 consecutive n-points; args computed as f32x2 pairs.
// ---------------------------------------------------------------------------
__global__ __launch_bounds__(TPB) void gauss_kernel() {
    __shared__ __align__(16) float smbuf[2][TM * RECF];   // 2 x 12 KB

    int s  = blockIdx.x;          // m-split
    int nt = blockIdx.y;          // n tile
    int b  = blockIdx.z;          // batch
    int t  = threadIdx.x;
    int n0 = nt * NTILE + t * RPT;

    const float* recs = g_recs + (size_t)b * NPTS * RECF;

    // Per-thread n features, packed as pairs (r0,r1) and (r2,r3)
    float4 A[RPT], E[RPT];
#pragma unroll
    for (int r = 0; r < RPT; r++) {
        const float4* rn = (const float4*)(recs + (size_t)(n0 + r) * RECF);
        A[r] = rn[0];  // g0..g3
        E[r] = rn[1];  // g4, c, pad, pad
    }
    unsigned long long gp[2][5], cpn[2];
#pragma unroll
    for (int r2 = 0; r2 < 2; r2++) {
        gp[r2][0] = packab(A[2 * r2].x, A[2 * r2 + 1].x);
        gp[r2][1] = packab(A[2 * r2].y, A[2 * r2 + 1].y);
        gp[r2][2] = packab(A[2 * r2].z, A[2 * r2 + 1].z);
        gp[r2][3] = packab(A[2 * r2].w, A[2 * r2 + 1].w);
        gp[r2][4] = packab(E[2 * r2].x, E[2 * r2 + 1].x);
        cpn[r2]   = packab(E[2 * r2].y, E[2 * r2 + 1].y);
    }

    unsigned long long acc[RPT][11];
#pragma unroll
    for (int r = 0; r < RPT; r++)
#pragma unroll
        for (int j = 0; j < 11; j++)
            acc[r][j] = 0ull;

    const float* gsrc = recs + (size_t)s * CHUNK * RECF;

    // prologue: stage 0 -> buf 0
    {
        uint32_t sb = (uint32_t)__cvta_generic_to_shared(&smbuf[0][0]);
#pragma unroll
        for (int k = 0; k < 3; k++) {
            int ci = t + k * TPB;                // 0..767 16B-chunks
            cp_async16(sb + ci * 16, gsrc + ci * 4);
        }
        cp_commit();
    }

    for (int st = 0; st < NSTAGES; st++) {
        __syncthreads();   // buffer (st+1)&1 no longer being read
        if (st + 1 < NSTAGES) {
            uint32_t sb = (uint32_t)__cvta_generic_to_shared(&smbuf[(st + 1) & 1][0]);
            const float* base = gsrc + (size_t)(st + 1) * TM * RECF;
#pragma unroll
            for (int k = 0; k < 3; k++) {
                int ci = t + k * TPB;
                cp_async16(sb + ci * 16, base + ci * 4);
            }
            cp_commit();
            cp_wait<1>();      // stage st complete (groups finish in order)
        } else {
            cp_wait<0>();
        }
        __syncthreads();

        const float* buf = &smbuf[st & 1][0];
#pragma unroll 1
        for (int mm = 0; mm < TM; mm++) {
            const float4* rp = (const float4*)(buf + mm * RECF);
            float4 a = rp[0];
            float4 e = rp[1];
            const ulonglong2* rv = (const ulonglong2*)(rp + 2);
            ulonglong2 v0 = rv[0];
            ulonglong2 v1 = rv[1];
            ulonglong2 v2 = rv[2];
            ulonglong2 v3 = rv[3];
            ulonglong2 v4 = rv[4];
            ulonglong2 v5 = rv[5];

            unsigned long long cm2 = pack2(e.y);
            unsigned long long g0m = pack2(a.x);
            unsigned long long g1m = pack2(a.y);
            unsigned long long g2m = pack2(a.z);
            unsigned long long g3m = pack2(a.w);
            unsigned long long g4m = pack2(e.x);

#pragma unroll
            for (int r2 = 0; r2 < 2; r2++) {
                unsigned long long arg = add2(cpn[r2], cm2);
                arg = fma2(gp[r2][0], g0m, arg);
                arg = fma2(gp[r2][1], g1m, arg);
                arg = fma2(gp[r2][2], g2m, arg);
                arg = fma2(gp[r2][3], g3m, arg);
                arg = fma2(gp[r2][4], g4m, arg);
                float a0, a1;
                unpack2(arg, a0, a1);
                unsigned long long k0 = pack2(ex2f(a0));
                unsigned long long k1 = pack2(ex2f(a1));
                int r = 2 * r2;
                acc[r][0]  = fma2(k0, v0.x, acc[r][0]);
                acc[r][1]  = fma2(k0, v0.y, acc[r][1]);
                acc[r][2]  = fma2(k0, v1.x, acc[r][2]);
                acc[r][3]  = fma2(k0, v1.y, acc[r][3]);
                acc[r][4]  = fma2(k0, v2.x, acc[r][4]);
                acc[r][5]  = fma2(k0, v2.y, acc[r][5]);
                acc[r][6]  = fma2(k0, v3.x, acc[r][6]);
                acc[r][7]  = fma2(k0, v3.y, acc[r][7]);
                acc[r][8]  = fma2(k0, v4.x, acc[r][8]);
                acc[r][9]  = fma2(k0, v4.y, acc[r][9]);
                acc[r][10] = fma2(k0, v5.x, acc[r][10]);
                r = 2 * r2 + 1;
                acc[r][0]  = fma2(k1, v0.x, acc[r][0]);
                acc[r][1]  = fma2(k1, v0.y, acc[r][1]);
                acc[r][2]  = fma2(k1, v1.x, acc[r][2]);
                acc[r][3]  = fma2(k1, v1.y, acc[r][3]);
                acc[r][4]  = fma2(k1, v2.x, acc[r][4]);
                acc[r][5]  = fma2(k1, v2.y, acc[r][5]);
                acc[r][6]  = fma2(k1, v3.x, acc[r][6]);
                acc[r][7]  = fma2(k1, v3.y, acc[r][7]);
                acc[r][8]  = fma2(k1, v4.x, acc[r][8]);
                acc[r][9]  = fma2(k1, v4.y, acc[r][9]);
                acc[r][10] = fma2(k1, v5.x, acc[r][10]);
            }
        }
    }

#pragma unroll
    for (int r = 0; r < RPT; r++) {
        unsigned long long* p = (unsigned long long*)
            (g_partial + (size_t)(((s * BATCH + b) * NPTS) + (n0 + r)) * PSTRIDE);
#pragma unroll
        for (int j = 0; j < 11; j++)
            p[j] = acc[r][j];
    }
}

// ---------------------------------------------------------------------------
// Pass 3: deterministic reduction over MSPLIT partials (+ transpose)
// ---------------------------------------------------------------------------
__global__ void reduce_kernel(float* __restrict__ out) {
    int idx = blockIdx.x * blockDim.x + threadIdx.x;
    if (idx >= BATCH * CH * NPTS) return;
    int n = idx % NPTS;
    int c = (idx / NPTS) % CH;
    int b = idx / (NPTS * CH);
    float sum = 0.0f;
#pragma unroll
    for (int s = 0; s < MSPLIT; s++)
        sum += g_partial[(size_t)(((s * BATCH + b) * NPTS) + n) * PSTRIDE + c];
    out[idx] = sum;
}

extern "C" void kernel_launch(void* const* d_in, const int* in_sizes, int n_in,
                              void* d_out, int out_size) {
    const float* cur_state = (const float*)d_in[0];   // [2,21,96,96]
    const float* img       = (const float*)d_in[1];   // [2,3,96,96]
    float* out             = (float*)d_out;           // [2,21,96,96]

    prep_kernel<<<(BATCH * NPTS + 255) / 256, 256>>>(cur_state, img);
    gauss_kernel<<<dim3(MSPLIT, NTILES, BATCH), TPB>>>();
    reduce_kernel<<<(BATCH * CH * NPTS + 255) / 256, 256>>>(out);
}

// round 7
// speedup vs baseline: 7.9299x; 1.9949x over previous
#include <cuda_runtime.h>
#include <cuda_bf16.h>
#include <cstdint>

// ---------------- fixed problem shapes ----------------
#define NPTS  9216
#define WW    96
#define BATCH 2
#define CH    21
#define CHP   24            // channels padded to 3 x n8
#define NT    72            // tiles of 128 points
#define TPB   256

// Per-tile packed panel in gmem/smem (4096 u32 = 16 KB):
//  [0,512)     BF hi : [pt 0..127][4 kpair u32]   (m-features, B-frag layout)
//  [512,1024)  BF lo
//  [1024,2560) V hi  : [mp 0..63][24 ch]  u32 = (v[2mp], v[2mp+1]) bf16x2
//  [2560,4096) V lo
__device__ __align__(16) uint32_t gP [BATCH * NT * 4096];
// A-side features: [b][pt][8]: hi 4 u32 then lo 4 u32 (A-frag layout)
__device__ __align__(16) uint32_t gAF[BATCH * NPTS * 8];

// ---------------- helpers ----------------
__device__ __forceinline__ float ex2f(float x) {
    float y; asm("ex2.approx.f32 %0, %1;" : "=f"(y) : "f"(x)); return y;
}
// pack two f32 -> bf16x2, e0 in LOW half, e1 in HIGH half
__device__ __forceinline__ uint32_t packbf(float e0, float e1) {
    uint32_t r; asm("cvt.rn.bf16x2.f32 %0, %1, %2;" : "=r"(r) : "f"(e1), "f"(e0)); return r;
}
__device__ __forceinline__ void mma8(float* d, uint32_t a0, uint32_t a1, uint32_t b0) {
    asm volatile("mma.sync.aligned.m16n8k8.row.col.f32.bf16.bf16.f32 "
        "{%0,%1,%2,%3}, {%4,%5}, {%6}, {%0,%1,%2,%3};"
        : "+f"(d[0]), "+f"(d[1]), "+f"(d[2]), "+f"(d[3])
        : "r"(a0), "r"(a1), "r"(b0));
}
__device__ __forceinline__ void mma16(float* d, const uint32_t* a, uint32_t b0, uint32_t b1) {
    asm volatile("mma.sync.aligned.m16n8k16.row.col.f32.bf16.bf16.f32 "
        "{%0,%1,%2,%3}, {%4,%5,%6,%7}, {%8,%9}, {%0,%1,%2,%3};"
        : "+f"(d[0]), "+f"(d[1]), "+f"(d[2]), "+f"(d[3])
        : "r"(a[0]), "r"(a[1]), "r"(a[2]), "r"(a[3]), "r"(b0), "r"(b1));
}
__device__ __forceinline__ void cp16(uint32_t s, const void* g) {
    asm volatile("cp.async.cg.shared.global [%0], [%1], 16;" :: "r"(s), "l"(g));
}
__device__ __forceinline__ void cp_commit() { asm volatile("cp.async.commit_group;" ::: "memory"); }
__device__ __forceinline__ void cp_wait0()  { asm volatile("cp.async.wait_group 0;" ::: "memory"); }

__device__ __forceinline__ uint32_t bfb(float f) {
    return (uint32_t)__bfloat16_as_ushort(__float2bfloat16(f));
}
__device__ __forceinline__ float bff(uint32_t b) {
    return __bfloat162float(__ushort_as_bfloat16((unsigned short)b));
}

// ---------------------------------------------------------------------------
// Prep 1: per-point features -> A-frag layout (gAF) + B-frag panel (gP)
// Feature vec (log2 domain, centered): dims [g0..g4, *, *, 0]
//   A row: dim5=c, dim6=1 ; B row: dim5=1, dim6=c  =>  dot = g.g + c_n + c_m
// ---------------------------------------------------------------------------
__global__ void prep_feat(const float* __restrict__ img) {
    int idx = blockIdx.x * blockDim.x + threadIdx.x;
    if (idx >= BATCH * NPTS) return;
    int b = idx / NPTS;
    int n = idx - b * NPTS;
    int y = n / WW;
    int x = n - y * WW;

    const float SQ = 1.2011224087864498f;   // sqrt(log2 e)
    float g[5];
    g[0] = ((float)y - 47.5f) * (SQ / 8.0f);
    g[1] = ((float)x - 47.5f) * (SQ / 8.0f);
    g[2] = (img[(b * 3 + 0) * NPTS + n] - 0.5f) * (2.0f * SQ);
    g[3] = (img[(b * 3 + 1) * NPTS + n] - 0.5f) * (2.0f * SQ);
    g[4] = (img[(b * 3 + 2) * NPTS + n] - 0.5f) * (2.0f * SQ);
    float c = -0.5f * (g[0]*g[0] + g[1]*g[1] + g[2]*g[2] + g[3]*g[3] + g[4]*g[4]);

    uint32_t h[6], l[6];
#pragma unroll
    for (int i = 0; i < 6; i++) {
        float f = (i < 5) ? g[i] : c;
        h[i] = bfb(f);
        l[i] = bfb(f - bff(h[i]));
    }
    const uint32_t ONE = 0x3F80u;

    // A-side (dim5=c, dim6=1)
    uint32_t* ap = gAF + (size_t)idx * 8;
    ap[0] = h[0] | (h[1] << 16);
    ap[1] = h[2] | (h[3] << 16);
    ap[2] = h[4] | (h[5] << 16);
    ap[3] = ONE;                       // (1, 0)
    ap[4] = l[0] | (l[1] << 16);
    ap[5] = l[2] | (l[3] << 16);
    ap[6] = l[4] | (l[5] << 16);
    ap[7] = 0u;                        // (0, 0)

    // B-side panel (dim5=1, dim6=c)
    int tile = n >> 7, pt = n & 127;
    uint32_t* bp = gP + (size_t)(b * NT + tile) * 4096;
    bp[pt * 4 + 0]       = h[0] | (h[1] << 16);
    bp[pt * 4 + 1]       = h[2] | (h[3] << 16);
    bp[pt * 4 + 2]       = h[4] | (ONE  << 16);
    bp[pt * 4 + 3]       = h[5];                 // (c, 0)
    bp[512 + pt * 4 + 0] = l[0] | (l[1] << 16);
    bp[512 + pt * 4 + 1] = l[2] | (l[3] << 16);
    bp[512 + pt * 4 + 2] = l[4];                 // (g4lo, 0)
    bp[512 + pt * 4 + 3] = l[5];                 // (clo, 0)
}

// ---------------------------------------------------------------------------
// Prep 2: V panels: [mp][ch] u32 = bf16x2(v[2mp], v[2mp+1]); hi then lo
// ---------------------------------------------------------------------------
__global__ void prep_v(const float* __restrict__ cur_state) {
    int idx = blockIdx.x * blockDim.x + threadIdx.x;
    if (idx >= BATCH * NT * CHP * 64) return;
    int mp = idx & 63;
    int ch = (idx >> 6) % CHP;
    int tb = idx / (64 * CHP);
    int b = tb / NT;
    int tile = tb - b * NT;

    float v0 = 0.0f, v1 = 0.0f;
    if (ch < CH) {
        const float* src = cur_state + ((size_t)(b * CH + ch)) * NPTS + tile * 128;
        v0 = src[2 * mp];
        v1 = src[2 * mp + 1];
    }
    uint32_t h0 = bfb(v0), h1 = bfb(v1);
    uint32_t l0 = bfb(v0 - bff(h0)), l1 = bfb(v1 - bff(h1));

    uint32_t* bp = gP + (size_t)(b * NT + tile) * 4096;
    bp[1024 + mp * CHP + ch] = h0 | (h1 << 16);
    bp[2560 + mp * CHP + ch] = l0 | (l1 << 16);
}

// ---------------------------------------------------------------------------
// Main: flash-style  S = F_n . F_m^T  ->  K = ex2(S)  ->  O += K . V
// 8 warps x 16 rows; mma.sync bf16 (hi/lo 3-pass splits on both GEMMs)
// ---------------------------------------------------------------------------
__global__ __launch_bounds__(TPB, 1) void gauss_mma(float* __restrict__ out) {
    __shared__ __align__(16) uint32_t sbuf[2][4096];   // 2 x 16 KB

    const int nt   = blockIdx.x;
    const int b    = blockIdx.y;
    const int tid  = threadIdx.x;
    const int w    = tid >> 5;
    const int lane = tid & 31;
    const int qr   = lane >> 2;    // 0..7
    const int qc   = lane & 3;     // 0..3
    const int row  = w * 16 + qr;  // n-row (of 128) this thread's c0/c1 live in

    // A-side feature fragments (fixed for all tiles)
    const uint32_t* af0 = gAF + (size_t)(b * NPTS + nt * 128 + row) * 8;
    const uint32_t* af1 = gAF + (size_t)(b * NPTS + nt * 128 + row + 8) * 8;
    uint32_t ahi0 = af0[qc],     ahi1 = af1[qc];
    uint32_t alo0 = af0[4 + qc], alo1 = af1[4 + qc];

    float o[2][3][4];
#pragma unroll
    for (int p = 0; p < 2; p++)
#pragma unroll
        for (int nb = 0; nb < 3; nb++)
#pragma unroll
            for (int i = 0; i < 4; i++) o[p][nb][i] = 0.0f;

    const uint32_t* gsrc = gP + (size_t)(b * NT) * 4096;

    // prefetch tile 0 -> buf 0
    {
        uint32_t sb = (uint32_t)__cvta_generic_to_shared(&sbuf[0][0]);
#pragma unroll
        for (int k = 0; k < 4; k++) {
            int ci = tid + k * TPB;
            cp16(sb + ci * 16, gsrc + ci * 4);
        }
        cp_commit();
    }

    for (int t = 0; t < NT; t++) {
        cp_wait0();
        __syncthreads();
        if (t + 1 < NT) {
            uint32_t sb = (uint32_t)__cvta_generic_to_shared(&sbuf[(t + 1) & 1][0]);
            const uint32_t* src = gsrc + (size_t)(t + 1) * 4096;
#pragma unroll
            for (int k = 0; k < 4; k++) {
                int ci = tid + k * TPB;
                cp16(sb + ci * 16, src + ci * 4);
            }
            cp_commit();
        }

        const uint32_t* buf = &sbuf[t & 1][0];

        // ---- S GEMM: 16 n8-blocks of m, K=8, 3 split passes ----
        float s[16][4];
#pragma unroll
        for (int j = 0; j < 16; j++) {
            s[j][0] = s[j][1] = s[j][2] = s[j][3] = 0.0f;
            int pt = 8 * j + qr;           // m-point (B n-col = lane>>2)
            uint32_t bhi = buf[pt * 4 + qc];
            uint32_t blo = buf[512 + pt * 4 + qc];
            mma8(s[j], ahi0, ahi1, bhi);
            mma8(s[j], ahi0, ahi1, blo);
            mma8(s[j], alo0, alo1, bhi);
        }

        // ---- epilogue + V GEMM per 16-wide k-block ----
#pragma unroll
        for (int kb = 0; kb < 8; kb++) {
            float* s0 = s[2 * kb];
            float* s1 = s[2 * kb + 1];
            float e0 = ex2f(s0[0]), e1 = ex2f(s0[1]), e2 = ex2f(s0[2]), e3 = ex2f(s0[3]);
            float f0 = ex2f(s1[0]), f1 = ex2f(s1[1]), f2 = ex2f(s1[2]), f3 = ex2f(s1[3]);
            uint32_t khi[4], klo[4];
            khi[0] = packbf(e0, e1);
            khi[1] = packbf(e2, e3);
            khi[2] = packbf(f0, f1);
            khi[3] = packbf(f2, f3);
            klo[0] = packbf(e0 - __uint_as_float(khi[0] << 16),
                            e1 - __uint_as_float(khi[0] & 0xFFFF0000u));
            klo[1] = packbf(e2 - __uint_as_float(khi[1] << 16),
                            e3 - __uint_as_float(khi[1] & 0xFFFF0000u));
            klo[2] = packbf(f0 - __uint_as_float(khi[2] << 16),
                            f1 - __uint_as_float(khi[2] & 0xFFFF0000u));
            klo[3] = packbf(f2 - __uint_as_float(khi[3] << 16),
                            f3 - __uint_as_float(khi[3] & 0xFFFF0000u));

            int mp0 = 8 * kb + qc;         // B k-rows: mpairs mp0 and mp0+4
#pragma unroll
            for (int nb = 0; nb < 3; nb++) {
                int chx = 8 * nb + qr;
                uint32_t vh0 = buf[1024 + mp0 * CHP + chx];
                uint32_t vh1 = buf[1024 + (mp0 + 4) * CHP + chx];
                uint32_t vl0 = buf[2560 + mp0 * CHP + chx];
                uint32_t vl1 = buf[2560 + (mp0 + 4) * CHP + chx];
                float* acc = o[kb & 1][nb];
                mma16(acc, khi, vh0, vh1);
                mma16(acc, khi, vl0, vl1);
                mma16(acc, klo, vh0, vh1);
            }
        }
    }

    // ---- writeback: O[row, ch] (rows row, row+8; ch = 8nb + 2qc + {0,1}) ----
    float* ob = out + (size_t)b * CH * NPTS + (size_t)nt * 128;
#pragma unroll
    for (int nb = 0; nb < 3; nb++) {
        int ch0 = 8 * nb + 2 * qc;
        float v0 = o[0][nb][0] + o[1][nb][0];
        float v1 = o[0][nb][1] + o[1][nb][1];
        float v2 = o[0][nb][2] + o[1][nb][2];
        float v3 = o[0][nb][3] + o[1][nb][3];
        if (ch0 < CH) {
            ob[(size_t)ch0 * NPTS + row]     = v0;
            ob[(size_t)ch0 * NPTS + row + 8] = v2;
        }
        if (ch0 + 1 < CH) {
            ob[(size_t)(ch0 + 1) * NPTS + row]     = v1;
            ob[(size_t)(ch0 + 1) * NPTS + row + 8] = v3;
        }
    }
}

// ---------------------------------------------------------------------------
extern "C" void kernel_launch(void* const* d_in, const int* in_sizes, int n_in,
                              void* d_out, int out_size) {
    const float* cur_state = (const float*)d_in[0];   // [2,21,96,96]
    const float* img       = (const float*)d_in[1];   // [2,3,96,96]
    float* out             = (float*)d_out;           // [2,21,96,96]

    prep_feat<<<(BATCH * NPTS + 255) / 256, 256>>>(img);
    prep_v<<<(BATCH * NT * CHP * 64 + 255) / 256, 256>>>(cur_state);
    gauss_mma<<<dim3(NT, BATCH), TPB>>>(out);
}

// round 9
// speedup vs baseline: 8.5280x; 1.0754x over previous
#include <cuda_runtime.h>
#include <cuda_fp16.h>
#include <cstdint>

// ---------------- fixed problem shapes ----------------
#define NPTS  9216
#define WW    96
#define BATCH 2
#define CH    21
#define CHP   24            // channels padded to 3 x n8
#define NT    72            // tiles of 128 points
#define TPB   256
#define PSTR  3072          // u32 per tile panel (12 KB, padded from 2560)

// Per-tile packed panel in gmem/smem (PSTR u32):
//  [0,512)     BF hi : [pt 0..127][4 kpair u32]   (m-features, fp16 B-frag layout)
//  [512,1024)  BF lo
//  [1024,2560) V     : [mp 0..63][24 ch]  u32 = half2(v[2mp], v[2mp+1])
//  [2560,3072) pad
__device__ __align__(16) uint32_t gP [BATCH * NT * PSTR];
// A-side features: [b][pt][8]: hi 4 u32 then lo 4 u32 (fp16 A-frag layout)
__device__ __align__(16) uint32_t gAF[BATCH * NPTS * 8];

// ---------------- helpers ----------------
__device__ __forceinline__ float ex2f(float x) {
    float y; asm("ex2.approx.f32 %0, %1;" : "=f"(y) : "f"(x)); return y;
}
// pack two f32 -> f16x2, e0 in LOW half, e1 in HIGH half
__device__ __forceinline__ uint32_t packh(float e0, float e1) {
    uint32_t r; asm("cvt.rn.f16x2.f32 %0, %1, %2;" : "=r"(r) : "f"(e1), "f"(e0)); return r;
}
__device__ __forceinline__ void mma8(float* d, uint32_t a0, uint32_t a1, uint32_t b0) {
    asm volatile("mma.sync.aligned.m16n8k8.row.col.f32.f16.f16.f32 "
        "{%0,%1,%2,%3}, {%4,%5}, {%6}, {%0,%1,%2,%3};"
        : "+f"(d[0]), "+f"(d[1]), "+f"(d[2]), "+f"(d[3])
        : "r"(a0), "r"(a1), "r"(b0));
}
__device__ __forceinline__ void mma16(float* d, const uint32_t* a, uint32_t b0, uint32_t b1) {
    asm volatile("mma.sync.aligned.m16n8k16.row.col.f32.f16.f16.f32 "
        "{%0,%1,%2,%3}, {%4,%5,%6,%7}, {%8,%9}, {%0,%1,%2,%3};"
        : "+f"(d[0]), "+f"(d[1]), "+f"(d[2]), "+f"(d[3])
        : "r"(a[0]), "r"(a[1]), "r"(a[2]), "r"(a[3]), "r"(b0), "r"(b1));
}
__device__ __forceinline__ void cp16(uint32_t s, const void* g) {
    asm volatile("cp.async.cg.shared.global [%0], [%1], 16;" :: "r"(s), "l"(g));
}
__device__ __forceinline__ void cp_commit() { asm volatile("cp.async.commit_group;" ::: "memory"); }
__device__ __forceinline__ void cp_wait0()  { asm volatile("cp.async.wait_group 0;" ::: "memory"); }

__device__ __forceinline__ uint32_t h16(float f) {
    return (uint32_t)__half_as_ushort(__float2half_rn(f));
}
__device__ __forceinline__ float h2f(uint32_t b) {
    return __half2float(__ushort_as_half((unsigned short)b));
}

// ---------------------------------------------------------------------------
// Prep 1: per-point features -> A-frag layout (gAF) + B-frag panel (gP)
// Feature vec (log2 domain, centered): dims [g0..g4, *, *, 0]
//   A row: dim5=c, dim6=1 ; B row: dim5=1, dim6=c  =>  dot = g.g + c_n + c_m
// ---------------------------------------------------------------------------
__global__ void prep_feat(const float* __restrict__ img) {
    int idx = blockIdx.x * blockDim.x + threadIdx.x;
    if (idx >= BATCH * NPTS) return;
    int b = idx / NPTS;
    int n = idx - b * NPTS;
    int y = n / WW;
    int x = n - y * WW;

    const float SQ = 1.2011224087864498f;   // sqrt(log2 e)
    float g[5];
    g[0] = ((float)y - 47.5f) * (SQ / 8.0f);
    g[1] = ((float)x - 47.5f) * (SQ / 8.0f);
    g[2] = (img[(b * 3 + 0) * NPTS + n] - 0.5f) * (2.0f * SQ);
    g[3] = (img[(b * 3 + 1) * NPTS + n] - 0.5f) * (2.0f * SQ);
    g[4] = (img[(b * 3 + 2) * NPTS + n] - 0.5f) * (2.0f * SQ);
    float c = -0.5f * (g[0]*g[0] + g[1]*g[1] + g[2]*g[2] + g[3]*g[3] + g[4]*g[4]);

    uint32_t h[6], l[6];
#pragma unroll
    for (int i = 0; i < 6; i++) {
        float f = (i < 5) ? g[i] : c;
        h[i] = h16(f);
        l[i] = h16(f - h2f(h[i]));
    }
    const uint32_t ONE = 0x3C00u;   // fp16(1.0)

    // A-side (dim5=c, dim6=1)
    uint32_t* ap = gAF + (size_t)idx * 8;
    ap[0] = h[0] | (h[1] << 16);
    ap[1] = h[2] | (h[3] << 16);
    ap[2] = h[4] | (h[5] << 16);
    ap[3] = ONE;                       // (1, 0)
    ap[4] = l[0] | (l[1] << 16);
    ap[5] = l[2] | (l[3] << 16);
    ap[6] = l[4] | (l[5] << 16);
    ap[7] = 0u;                        // (0, 0)

    // B-side panel (dim5=1, dim6=c)
    int tile = n >> 7, pt = n & 127;
    uint32_t* bp = gP + (size_t)(b * NT + tile) * PSTR;
    bp[pt * 4 + 0]       = h[0] | (h[1] << 16);
    bp[pt * 4 + 1]       = h[2] | (h[3] << 16);
    bp[pt * 4 + 2]       = h[4] | (ONE  << 16);
    bp[pt * 4 + 3]       = h[5];                 // (c, 0)
    bp[512 + pt * 4 + 0] = l[0] | (l[1] << 16);
    bp[512 + pt * 4 + 1] = l[2] | (l[3] << 16);
    bp[512 + pt * 4 + 2] = l[4];                 // (g4lo, 0)
    bp[512 + pt * 4 + 3] = l[5];                 // (clo, 0)
}

// ---------------------------------------------------------------------------
// Prep 2: V panel: [mp][ch] u32 = half2(v[2mp], v[2mp+1]); also zero pad
// ---------------------------------------------------------------------------
__global__ void prep_v(const float* __restrict__ cur_state) {
    int idx = blockIdx.x * blockDim.x + threadIdx.x;
    if (idx >= BATCH * NT * CHP * 64) return;
    int mp = idx & 63;
    int ch = (idx >> 6) % CHP;
    int tb = idx / (64 * CHP);
    int b = tb / NT;
    int tile = tb - b * NT;

    float v0 = 0.0f, v1 = 0.0f;
    if (ch < CH) {
        const float* src = cur_state + ((size_t)(b * CH + ch)) * NPTS + tile * 128;
        v0 = src[2 * mp];
        v1 = src[2 * mp + 1];
    }
    uint32_t* bp = gP + (size_t)(b * NT + tile) * PSTR;
    bp[1024 + mp * CHP + ch] = h16(v0) | (h16(v1) << 16);
    // zero the pad region once per tile (first 512 threads of each tile's range)
    int li = (ch * 64 + mp);
    if (li < 512) bp[2560 + li] = 0u;
}

// ---------------------------------------------------------------------------
// Main: flash-style  S = F_n . F_m^T  ->  K = ex2(S)  ->  O += K . V
// 8 warps x 16 rows; mma.sync fp16 (hi/lo 3-pass on S, single pass on V)
// ---------------------------------------------------------------------------
__global__ __launch_bounds__(TPB, 1) void gauss_mma(float* __restrict__ out) {
    __shared__ __align__(16) uint32_t sbuf[2][PSTR];   // 2 x 12 KB

    const int nt   = blockIdx.x;
    const int b    = blockIdx.y;
    const int tid  = threadIdx.x;
    const int w    = tid >> 5;
    const int lane = tid & 31;
    const int qr   = lane >> 2;    // 0..7
    const int qc   = lane & 3;     // 0..3
    const int row  = w * 16 + qr;  // n-row (of 128) this thread covers (and +8)

    // A-side feature fragments (fixed for all tiles)
    const uint32_t* af0 = gAF + (size_t)(b * NPTS + nt * 128 + row) * 8;
    const uint32_t* af1 = gAF + (size_t)(b * NPTS + nt * 128 + row + 8) * 8;
    uint32_t ahi0 = af0[qc],     ahi1 = af1[qc];
    uint32_t alo0 = af0[4 + qc], alo1 = af1[4 + qc];

    float o[2][3][4];
#pragma unroll
    for (int p = 0; p < 2; p++)
#pragma unroll
        for (int nb = 0; nb < 3; nb++)
#pragma unroll
            for (int i = 0; i < 4; i++) o[p][nb][i] = 0.0f;

    const uint32_t* gsrc = gP + (size_t)(b * NT) * PSTR;

    // prefetch tile 0 -> buf 0
    {
        uint32_t sb = (uint32_t)__cvta_generic_to_shared(&sbuf[0][0]);
#pragma unroll
        for (int k = 0; k < 3; k++) {
            int ci = tid + k * TPB;
            cp16(sb + ci * 16, gsrc + ci * 4);
        }
        cp_commit();
    }

    for (int t = 0; t < NT; t++) {
        cp_wait0();
        __syncthreads();
        if (t + 1 < NT) {
            uint32_t sb = (uint32_t)__cvta_generic_to_shared(&sbuf[(t + 1) & 1][0]);
            const uint32_t* src = gsrc + (size_t)(t + 1) * PSTR;
#pragma unroll
            for (int k = 0; k < 3; k++) {
                int ci = tid + k * TPB;
                cp16(sb + ci * 16, src + ci * 4);
            }
            cp_commit();
        }

        const uint32_t* buf = &sbuf[t & 1][0];

        // ---- S GEMM: 16 n8-blocks of m, K=8, 3 split passes ----
        float s[16][4];
#pragma unroll
        for (int j = 0; j < 16; j++) {
            s[j][0] = s[j][1] = s[j][2] = s[j][3] = 0.0f;
            int pt = 8 * j + qr;           // m-point feeding B-frag
            uint32_t bhi = buf[pt * 4 + qc];
            uint32_t blo = buf[512 + pt * 4 + qc];
            mma8(s[j], ahi0, ahi1, bhi);
            mma8(s[j], ahi0, ahi1, blo);
            mma8(s[j], alo0, alo1, bhi);
        }

        // ---- epilogue + single-pass V GEMM per 16-wide k-block ----
#pragma unroll
        for (int kb = 0; kb < 8; kb++) {
            float* s0 = s[2 * kb];
            float* s1 = s[2 * kb + 1];
            uint32_t kh[4];
            kh[0] = packh(ex2f(s0[0]), ex2f(s0[1]));
            kh[1] = packh(ex2f(s0[2]), ex2f(s0[3]));
            kh[2] = packh(ex2f(s1[0]), ex2f(s1[1]));
            kh[3] = packh(ex2f(s1[2]), ex2f(s1[3]));

            int mp0 = 8 * kb + qc;         // B k-rows: mpairs mp0 and mp0+4
#pragma unroll
            for (int nb = 0; nb < 3; nb++) {
                int chx = 8 * nb + qr;
                uint32_t v0 = buf[1024 + mp0 * CHP + chx];
                uint32_t v1 = buf[1024 + (mp0 + 4) * CHP + chx];
                mma16(o[kb & 1][nb], kh, v0, v1);
            }
        }
    }

    // ---- writeback: rows (row, row+8), ch = 8nb + 2qc + {0,1} ----
    float* ob = out + (size_t)b * CH * NPTS + (size_t)nt * 128;
#pragma unroll
    for (int nb = 0; nb < 3; nb++) {
        int ch0 = 8 * nb + 2 * qc;
        float v0 = o[0][nb][0] + o[1][nb][0];
        float v1 = o[0][nb][1] + o[1][nb][1];
        float v2 = o[0][nb][2] + o[1][nb][2];
        float v3 = o[0][nb][3] + o[1][nb][3];
        if (ch0 < CH) {
            ob[(size_t)ch0 * NPTS + row]     = v0;
            ob[(size_t)ch0 * NPTS + row + 8] = v2;
        }
        if (ch0 + 1 < CH) {
            ob[(size_t)(ch0 + 1) * NPTS + row]     = v1;
            ob[(size_t)(ch0 + 1) * NPTS + row + 8] = v3;
        }
    }
}

// ---------------------------------------------------------------------------
extern "C" void kernel_launch(void* const* d_in, const int* in_sizes, int n_in,
                              void* d_out, int out_size) {
    const float* cur_state = (const float*)d_in[0];   // [2,21,96,96]
    const float* img       = (const float*)d_in[1];   // [2,3,96,96]
    float* out             = (float*)d_out;           // [2,21,96,96]

    prep_feat<<<(BATCH * NPTS + 255) / 256, 256>>>(img);
    prep_v<<<(BATCH * NT * CHP * 64 + 255) / 256, 256>>>(cur_state);
    gauss_mma<<<dim3(NT, BATCH), TPB>>>(out);
}

// round 12
// speedup vs baseline: 13.1767x; 1.5451x over previous
#include <cuda_runtime.h>
#include <cuda_fp16.h>
#include <cstdint>

// ---------------- fixed problem shapes ----------------
#define NPTS  9216
#define WW    96
#define BATCH 2
#define CH    21
#define CHP   24            // channels padded to 3 x n8
#define NT    72            // m-tiles of 128 points
#define MSPL  2             // m-range splits (occupancy 2 CTAs/SM)
#define NT2   (NT / MSPL)   // 36 m-tiles per CTA
#define TPB   256
#define PSTR  3072          // u32 per tile panel (12 KB)

// Per-tile packed panel in gmem/smem (PSTR u32):
//  [0,512)     BF hi : [pt 0..127][4 kpair u32]   (m-features, fp16 B-frag layout)
//  [512,1024)  BF lo
//  [1024,2560) V     : [mp 0..63][24 ch]  u32 = half2(v[2mp], v[2mp+1])
//  [2560,3072) pad
__device__ __align__(16) uint32_t gP [BATCH * NT * PSTR];
// A-side features: [b][pt][8]: hi 4 u32 then lo 4 u32 (fp16 A-frag layout)
__device__ __align__(16) uint32_t gAF[BATCH * NPTS * 8];
// partial outputs: [split][b][ch(24)][n]
__device__ __align__(16) float gPart[MSPL * BATCH * CHP * NPTS];

// ---------------- helpers ----------------
__device__ __forceinline__ float ex2f(float x) {
    float y; asm("ex2.approx.f32 %0, %1;" : "=f"(y) : "f"(x)); return y;
}
// pack two f32 -> f16x2, e0 in LOW half, e1 in HIGH half
__device__ __forceinline__ uint32_t packh(float e0, float e1) {
    uint32_t r; asm("cvt.rn.f16x2.f32 %0, %1, %2;" : "=r"(r) : "f"(e1), "f"(e0)); return r;
}
__device__ __forceinline__ void mma8(float* d, uint32_t a0, uint32_t a1, uint32_t b0) {
    asm volatile("mma.sync.aligned.m16n8k8.row.col.f32.f16.f16.f32 "
        "{%0,%1,%2,%3}, {%4,%5}, {%6}, {%0,%1,%2,%3};"
        : "+f"(d[0]), "+f"(d[1]), "+f"(d[2]), "+f"(d[3])
        : "r"(a0), "r"(a1), "r"(b0));
}
__device__ __forceinline__ void mma16(float* d, const uint32_t* a, uint32_t b0, uint32_t b1) {
    asm volatile("mma.sync.aligned.m16n8k16.row.col.f32.f16.f16.f32 "
        "{%0,%1,%2,%3}, {%4,%5,%6,%7}, {%8,%9}, {%0,%1,%2,%3};"
        : "+f"(d[0]), "+f"(d[1]), "+f"(d[2]), "+f"(d[3])
        : "r"(a[0]), "r"(a[1]), "r"(a[2]), "r"(a[3]), "r"(b0), "r"(b1));
}
__device__ __forceinline__ void cp16(uint32_t s, const void* g) {
    asm volatile("cp.async.cg.shared.global [%0], [%1], 16;" :: "r"(s), "l"(g));
}
__device__ __forceinline__ void cp_commit() { asm volatile("cp.async.commit_group;" ::: "memory"); }
__device__ __forceinline__ void cp_wait0()  { asm volatile("cp.async.wait_group 0;" ::: "memory"); }

__device__ __forceinline__ uint32_t h16(float f) {
    return (uint32_t)__half_as_ushort(__float2half_rn(f));
}
__device__ __forceinline__ float h2f(uint32_t b) {
    return __half2float(__ushort_as_half((unsigned short)b));
}

// ---------------------------------------------------------------------------
// Prep 1: per-point features -> A-frag layout (gAF) + B-frag panel (gP)
//   A row: dim5=c, dim6=1 ; B row: dim5=1, dim6=c  =>  dot = g.g + c_n + c_m
// ---------------------------------------------------------------------------
__global__ void prep_feat(const float* __restrict__ img) {
    int idx = blockIdx.x * blockDim.x + threadIdx.x;
    if (idx >= BATCH * NPTS) return;
    int b = idx / NPTS;
    int n = idx - b * NPTS;
    int y = n / WW;
    int x = n - y * WW;

    const float SQ = 1.2011224087864498f;   // sqrt(log2 e)
    float g[5];
    g[0] = ((float)y - 47.5f) * (SQ / 8.0f);
    g[1] = ((float)x - 47.5f) * (SQ / 8.0f);
    g[2] = (img[(b * 3 + 0) * NPTS + n] - 0.5f) * (2.0f * SQ);
    g[3] = (img[(b * 3 + 1) * NPTS + n] - 0.5f) * (2.0f * SQ);
    g[4] = (img[(b * 3 + 2) * NPTS + n] - 0.5f) * (2.0f * SQ);
    float c = -0.5f * (g[0]*g[0] + g[1]*g[1] + g[2]*g[2] + g[3]*g[3] + g[4]*g[4]);

    uint32_t h[6], l[6];
#pragma unroll
    for (int i = 0; i < 6; i++) {
        float f = (i < 5) ? g[i] : c;
        h[i] = h16(f);
        l[i] = h16(f - h2f(h[i]));
    }
    const uint32_t ONE = 0x3C00u;   // fp16(1.0)

    uint32_t* ap = gAF + (size_t)idx * 8;
    ap[0] = h[0] | (h[1] << 16);
    ap[1] = h[2] | (h[3] << 16);
    ap[2] = h[4] | (h[5] << 16);
    ap[3] = ONE;                       // (1, 0)
    ap[4] = l[0] | (l[1] << 16);
    ap[5] = l[2] | (l[3] << 16);
    ap[6] = l[4] | (l[5] << 16);
    ap[7] = 0u;                        // (0, 0)

    int tile = n >> 7, pt = n & 127;
    uint32_t* bp = gP + (size_t)(b * NT + tile) * PSTR;
    bp[pt * 4 + 0]       = h[0] | (h[1] << 16);
    bp[pt * 4 + 1]       = h[2] | (h[3] << 16);
    bp[pt * 4 + 2]       = h[4] | (ONE  << 16);
    bp[pt * 4 + 3]       = h[5];                 // (c, 0)
    bp[512 + pt * 4 + 0] = l[0] | (l[1] << 16);
    bp[512 + pt * 4 + 1] = l[2] | (l[3] << 16);
    bp[512 + pt * 4 + 2] = l[4];
    bp[512 + pt * 4 + 3] = l[5];
}

// ---------------------------------------------------------------------------
// Prep 2: V panel: [mp][ch] u32 = half2(v[2mp], v[2mp+1]); zero pad region
// ---------------------------------------------------------------------------
__global__ void prep_v(const float* __restrict__ cur_state) {
    int idx = blockIdx.x * blockDim.x + threadIdx.x;
    if (idx >= BATCH * NT * CHP * 64) return;
    int mp = idx & 63;
    int ch = (idx >> 6) % CHP;
    int tb = idx / (64 * CHP);
    int b = tb / NT;
    int tile = tb - b * NT;

    float v0 = 0.0f, v1 = 0.0f;
    if (ch < CH) {
        const float* src = cur_state + ((size_t)(b * CH + ch)) * NPTS + tile * 128;
        v0 = src[2 * mp];
        v1 = src[2 * mp + 1];
    }
    uint32_t* bp = gP + (size_t)(b * NT + tile) * PSTR;
    bp[1024 + mp * CHP + ch] = h16(v0) | (h16(v1) << 16);
    int li = (ch * 64 + mp);
    if (li < 512) bp[2560 + li] = 0u;
}

// ---------------------------------------------------------------------------
// Main: flash-style  S -> ex2 -> O, m-split x2 for occupancy, per-kb fusion
// ---------------------------------------------------------------------------
__global__ __launch_bounds__(TPB, 2) void gauss_mma() {
    __shared__ __align__(16) uint32_t sbuf[2][PSTR];   // 2 x 12 KB

    const int nt   = blockIdx.x;    // n tile
    const int sp   = blockIdx.y;    // m split
    const int b    = blockIdx.z;    // batch
    const int tid  = threadIdx.x;
    const int w    = tid >> 5;
    const int lane = tid & 31;
    const int qr   = lane >> 2;    // 0..7
    const int qc   = lane & 3;     // 0..3
    const int row  = w * 16 + qr;  // n-row (of 128) this thread covers (and +8)

    const uint32_t* af0 = gAF + (size_t)(b * NPTS + nt * 128 + row) * 8;
    const uint32_t* af1 = gAF + (size_t)(b * NPTS + nt * 128 + row + 8) * 8;
    uint32_t ahi0 = af0[qc],     ahi1 = af1[qc];
    uint32_t alo0 = af0[4 + qc], alo1 = af1[4 + qc];

    float o[2][3][4];
#pragma unroll
    for (int p = 0; p < 2; p++)
#pragma unroll
        for (int nb = 0; nb < 3; nb++)
#pragma unroll
            for (int i = 0; i < 4; i++) o[p][nb][i] = 0.0f;

    const uint32_t* gsrc = gP + (size_t)(b * NT + sp * NT2) * PSTR;

    {   // prefetch first tile -> buf 0
        uint32_t sb = (uint32_t)__cvta_generic_to_shared(&sbuf[0][0]);
#pragma unroll
        for (int k = 0; k < 3; k++) {
            int ci = tid + k * TPB;
            cp16(sb + ci * 16, gsrc + ci * 4);
        }
        cp_commit();
    }

    for (int t = 0; t < NT2; t++) {
        cp_wait0();
        __syncthreads();
        if (t + 1 < NT2) {
            uint32_t sb = (uint32_t)__cvta_generic_to_shared(&sbuf[(t + 1) & 1][0]);
            const uint32_t* src = gsrc + (size_t)(t + 1) * PSTR;
#pragma unroll
            for (int k = 0; k < 3; k++) {
                int ci = tid + k * TPB;
                cp16(sb + ci * 16, src + ci * 4);
            }
            cp_commit();
        }

        const uint32_t* buf = &sbuf[t & 1][0];

        // fused per-kb: S (6 mma8) -> ex2/pack -> V (3 mma16)
#pragma unroll
        for (int kb = 0; kb < 8; kb++) {
            int pt0 = 16 * kb + qr;
            uint32_t bhi0 = buf[pt0 * 4 + qc];
            uint32_t blo0 = buf[512 + pt0 * 4 + qc];
            uint32_t bhi1 = buf[(pt0 + 8) * 4 + qc];
            uint32_t blo1 = buf[512 + (pt0 + 8) * 4 + qc];

            float s0[4] = {0.f, 0.f, 0.f, 0.f};
            float s1[4] = {0.f, 0.f, 0.f, 0.f};
            mma8(s0, ahi0, ahi1, bhi0);
            mma8(s1, ahi0, ahi1, bhi1);
            mma8(s0, ahi0, ahi1, blo0);
            mma8(s1, ahi0, ahi1, blo1);
            mma8(s0, alo0, alo1, bhi0);
            mma8(s1, alo0, alo1, bhi1);

            uint32_t kh[4];
            kh[0] = packh(ex2f(s0[0]), ex2f(s0[1]));
            kh[1] = packh(ex2f(s0[2]), ex2f(s0[3]));
            kh[2] = packh(ex2f(s1[0]), ex2f(s1[1]));
            kh[3] = packh(ex2f(s1[2]), ex2f(s1[3]));

            int mp0 = 8 * kb + qc;
#pragma unroll
            for (int nb = 0; nb < 3; nb++) {
                int chx = 8 * nb + qr;
                uint32_t v0 = buf[1024 + mp0 * CHP + chx];
                uint32_t v1 = buf[1024 + (mp0 + 4) * CHP + chx];
                mma16(o[kb & 1][nb], kh, v0, v1);
            }
        }
    }

    // ---- writeback partials: rows (row, row+8), ch = 8nb + 2qc + {0,1} ----
    float* pb = gPart + ((size_t)(sp * BATCH + b) * CHP) * NPTS + (size_t)nt * 128;
#pragma unroll
    for (int nb = 0; nb < 3; nb++) {
        int ch0 = 8 * nb + 2 * qc;
        pb[(size_t)ch0 * NPTS + row]           = o[0][nb][0] + o[1][nb][0];
        pb[(size_t)(ch0 + 1) * NPTS + row]     = o[0][nb][1] + o[1][nb][1];
        pb[(size_t)ch0 * NPTS + row + 8]       = o[0][nb][2] + o[1][nb][2];
        pb[(size_t)(ch0 + 1) * NPTS + row + 8] = o[0][nb][3] + o[1][nb][3];
    }
}

// ---------------------------------------------------------------------------
// Reduce: out[b][c][n] = part[0] + part[1]
// ---------------------------------------------------------------------------
__global__ void reduce_kernel(float* __restrict__ out) {
    int idx = blockIdx.x * blockDim.x + threadIdx.x;
    if (idx >= BATCH * CH * NPTS) return;
    int n = idx % NPTS;
    int c = (idx / NPTS) % CH;
    int b = idx / (NPTS * CH);
    float v = gPart[((size_t)(0 * BATCH + b) * CHP + c) * NPTS + n]
            + gPart[((size_t)(1 * BATCH + b) * CHP + c) * NPTS + n];
    out[idx] = v;
}

// ---------------------------------------------------------------------------
extern "C" void kernel_launch(void* const* d_in, const int* in_sizes, int n_in,
                              void* d_out, int out_size) {
    const float* cur_state = (const float*)d_in[0];   // [2,21,96,96]
    const float* img       = (const float*)d_in[1];   // [2,3,96,96]
    float* out             = (float*)d_out;           // [2,21,96,96]

    prep_feat<<<(BATCH * NPTS + 255) / 256, 256>>>(img);
    prep_v<<<(BATCH * NT * CHP * 64 + 255) / 256, 256>>>(cur_state);
    gauss_mma<<<dim3(NT, MSPL, BATCH), TPB>>>();
    reduce_kernel<<<(BATCH * CH * NPTS + 255) / 256, 256>>>(out);
}

// round 16
// speedup vs baseline: 13.4420x; 1.0201x over previous
#include <cuda_runtime.h>
#include <cuda_fp16.h>
#include <cstdint>

// ---------------- fixed problem shapes ----------------
#define NPTS  9216
#define WW    96
#define BATCH 2
#define CH    21
#define CHP   24            // channels padded to 3 x n8
#define NT    72            // m-tiles of 128 points
#define HALF_NT 36          // m-tiles per warp-group
#define TPB   512
#define PSTR  3072          // u32 per tile panel (12 KB)

// Per-tile packed panel in gmem/smem (PSTR u32):
//  [0,512)     BF hi : [pt 0..127][4 kpair u32]   (m-features, fp16 B-frag layout)
//  [512,1024)  BF lo
//  [1024,2560) V     : [mp 0..63][24 ch]  u32 = half2(v[2mp], v[2mp+1])
//  [2560,3072) pad
__device__ __align__(16) uint32_t gP [BATCH * NT * PSTR];
// A-side features: [b][pt][8]: hi 4 u32 then lo 4 u32 (fp16 A-frag layout)
__device__ __align__(16) uint32_t gAF[BATCH * NPTS * 8];

// ---------------- helpers ----------------
__device__ __forceinline__ float ex2f(float x) {
    float y; asm("ex2.approx.f32 %0, %1;" : "=f"(y) : "f"(x)); return y;
}
__device__ __forceinline__ uint32_t packh(float e0, float e1) {   // e0 LOW, e1 HIGH
    uint32_t r; asm("cvt.rn.f16x2.f32 %0, %1, %2;" : "=r"(r) : "f"(e1), "f"(e0)); return r;
}
__device__ __forceinline__ void mma8(float* d, uint32_t a0, uint32_t a1, uint32_t b0) {
    asm volatile("mma.sync.aligned.m16n8k8.row.col.f32.f16.f16.f32 "
        "{%0,%1,%2,%3}, {%4,%5}, {%6}, {%0,%1,%2,%3};"
        : "+f"(d[0]), "+f"(d[1]), "+f"(d[2]), "+f"(d[3])
        : "r"(a0), "r"(a1), "r"(b0));
}
__device__ __forceinline__ void mma16(float* d, const uint32_t* a, uint32_t b0, uint32_t b1) {
    asm volatile("mma.sync.aligned.m16n8k16.row.col.f32.f16.f16.f32 "
        "{%0,%1,%2,%3}, {%4,%5,%6,%7}, {%8,%9}, {%0,%1,%2,%3};"
        : "+f"(d[0]), "+f"(d[1]), "+f"(d[2]), "+f"(d[3])
        : "r"(a[0]), "r"(a[1]), "r"(a[2]), "r"(a[3]), "r"(b0), "r"(b1));
}
__device__ __forceinline__ void cp16(uint32_t s, const void* g) {
    asm volatile("cp.async.cg.shared.global [%0], [%1], 16;" :: "r"(s), "l"(g));
}
__device__ __forceinline__ void cp_commit() { asm volatile("cp.async.commit_group;" ::: "memory"); }
__device__ __forceinline__ void cp_wait0()  { asm volatile("cp.async.wait_group 0;" ::: "memory"); }

__device__ __forceinline__ uint32_t h16(float f) {
    return (uint32_t)__half_as_ushort(__float2half_rn(f));
}
__device__ __forceinline__ float h2f(uint32_t b) {
    return __half2float(__ushort_as_half((unsigned short)b));
}

// ---------------------------------------------------------------------------
// Fused prep: V panel pack (all threads) + feature pack (first BATCH*NPTS)
// ---------------------------------------------------------------------------
#define NV (BATCH * NT * CHP * 64)     // 221184
__global__ void prep_all(const float* __restrict__ cur_state,
                         const float* __restrict__ img) {
    int idx = blockIdx.x * blockDim.x + threadIdx.x;
    if (idx < NV) {
        int mp = idx & 63;
        int ch = (idx >> 6) % CHP;
        int tb = idx / (64 * CHP);
        int b = tb / NT;
        int tile = tb - b * NT;

        float v0 = 0.0f, v1 = 0.0f;
        if (ch < CH) {
            const float* src = cur_state + ((size_t)(b * CH + ch)) * NPTS + tile * 128;
            v0 = src[2 * mp];
            v1 = src[2 * mp + 1];
        }
        uint32_t* bp = gP + (size_t)(b * NT + tile) * PSTR;
        bp[1024 + mp * CHP + ch] = h16(v0) | (h16(v1) << 16);
        int li = (ch * 64 + mp);
        if (li < 512) bp[2560 + li] = 0u;
    }
    if (idx < BATCH * NPTS) {
        int b = idx / NPTS;
        int n = idx - b * NPTS;
        int y = n / WW;
        int x = n - y * WW;

        const float SQ = 1.2011224087864498f;   // sqrt(log2 e)
        float g[5];
        g[0] = ((float)y - 47.5f) * (SQ / 8.0f);
        g[1] = ((float)x - 47.5f) * (SQ / 8.0f);
        g[2] = (img[(b * 3 + 0) * NPTS + n] - 0.5f) * (2.0f * SQ);
        g[3] = (img[(b * 3 + 1) * NPTS + n] - 0.5f) * (2.0f * SQ);
        g[4] = (img[(b * 3 + 2) * NPTS + n] - 0.5f) * (2.0f * SQ);
        float c = -0.5f * (g[0]*g[0] + g[1]*g[1] + g[2]*g[2] + g[3]*g[3] + g[4]*g[4]);

        uint32_t h[6], l[6];
#pragma unroll
        for (int i = 0; i < 6; i++) {
            float f = (i < 5) ? g[i] : c;
            h[i] = h16(f);
            l[i] = h16(f - h2f(h[i]));
        }
        const uint32_t ONE = 0x3C00u;   // fp16(1.0)

        uint32_t* ap = gAF + (size_t)idx * 8;
        ap[0] = h[0] | (h[1] << 16);
        ap[1] = h[2] | (h[3] << 16);
        ap[2] = h[4] | (h[5] << 16);
        ap[3] = ONE;                       // (1, 0)
        ap[4] = l[0] | (l[1] << 16);
        ap[5] = l[2] | (l[3] << 16);
        ap[6] = l[4] | (l[5] << 16);
        ap[7] = 0u;                        // (0, 0)

        int tile = n >> 7, pt = n & 127;
        uint32_t* bp = gP + (size_t)(b * NT + tile) * PSTR;
        bp[pt * 4 + 0]       = h[0] | (h[1] << 16);
        bp[pt * 4 + 1]       = h[2] | (h[3] << 16);
        bp[pt * 4 + 2]       = h[4] | (ONE  << 16);
        bp[pt * 4 + 3]       = h[5];                 // (c, 0)
        bp[512 + pt * 4 + 0] = l[0] | (l[1] << 16);
        bp[512 + pt * 4 + 1] = l[2] | (l[3] << 16);
        bp[512 + pt * 4 + 2] = l[4];
        bp[512 + pt * 4 + 3] = l[5];
    }
}

// ---------------------------------------------------------------------------
// Main: 512 threads. Warp-group hw = tid/256 covers m-tiles [hw*36,(hw+1)*36);
// both groups share the 128 n-rows. Final intra-CTA smem reduce, direct out.
// Each tile panel = PSTR u32 = 12 KB = 768 16B-chunks -> 3 cp16 per thread (256).
// ---------------------------------------------------------------------------
__global__ __launch_bounds__(TPB, 1) void gauss_mma(float* __restrict__ out) {
    __shared__ __align__(16) uint32_t sbuf[2][2][PSTR];   // [half][stage], 48 KB

    const int nt   = blockIdx.x;    // n tile (0..71)
    const int b    = blockIdx.y;    // batch
    const int tid  = threadIdx.x;
    const int hw   = tid >> 8;      // m warp-group 0/1
    const int wtid = tid & 255;
    const int w    = wtid >> 5;     // warp within group (0..7)
    const int lane = tid & 31;
    const int qr   = lane >> 2;     // 0..7
    const int qc   = lane & 3;      // 0..3
    const int row  = w * 16 + qr;   // n-row this thread covers (and +8)

    const uint32_t* af0 = gAF + (size_t)(b * NPTS + nt * 128 + row) * 8;
    const uint32_t* af1 = gAF + (size_t)(b * NPTS + nt * 128 + row + 8) * 8;
    uint32_t ahi0 = af0[qc],     ahi1 = af1[qc];
    uint32_t alo0 = af0[4 + qc], alo1 = af1[4 + qc];

    float o[2][3][4];
#pragma unroll
    for (int p = 0; p < 2; p++)
#pragma unroll
        for (int nb = 0; nb < 3; nb++)
#pragma unroll
            for (int i = 0; i < 4; i++) o[p][nb][i] = 0.0f;

    const uint32_t* gsrc = gP + (size_t)(b * NT + hw * HALF_NT) * PSTR;

    {   // prefetch first tile of this half -> stage 0 (768 chunks / 256 threads)
        uint32_t sb = (uint32_t)__cvta_generic_to_shared(&sbuf[hw][0][0]);
#pragma unroll
        for (int k = 0; k < 3; k++) {
            int ci = wtid + k * 256;
            cp16(sb + ci * 16, gsrc + ci * 4);
        }
        cp_commit();
    }

    for (int t = 0; t < HALF_NT; t++) {
        cp_wait0();
        __syncthreads();
        if (t + 1 < HALF_NT) {
            uint32_t sb = (uint32_t)__cvta_generic_to_shared(&sbuf[hw][(t + 1) & 1][0]);
            const uint32_t* src = gsrc + (size_t)(t + 1) * PSTR;
#pragma unroll
            for (int k = 0; k < 3; k++) {
                int ci = wtid + k * 256;
                cp16(sb + ci * 16, src + ci * 4);
            }
            cp_commit();
        }

        const uint32_t* buf = &sbuf[hw][t & 1][0];

        // fused per-kb: S (6 mma8) -> ex2/pack -> V (3 mma16)
#pragma unroll
        for (int kb = 0; kb < 8; kb++) {
            int pt0 = 16 * kb + qr;
            uint32_t bhi0 = buf[pt0 * 4 + qc];
            uint32_t blo0 = buf[512 + pt0 * 4 + qc];
            uint32_t bhi1 = buf[(pt0 + 8) * 4 + qc];
            uint32_t blo1 = buf[512 + (pt0 + 8) * 4 + qc];

            float s0[4] = {0.f, 0.f, 0.f, 0.f};
            float s1[4] = {0.f, 0.f, 0.f, 0.f};
            mma8(s0, ahi0, ahi1, bhi0);
            mma8(s1, ahi0, ahi1, bhi1);
            mma8(s0, ahi0, ahi1, blo0);
            mma8(s1, ahi0, ahi1, blo1);
            mma8(s0, alo0, alo1, bhi0);
            mma8(s1, alo0, alo1, bhi1);

            uint32_t kh[4];
            kh[0] = packh(ex2f(s0[0]), ex2f(s0[1]));
            kh[1] = packh(ex2f(s0[2]), ex2f(s0[3]));
            kh[2] = packh(ex2f(s1[0]), ex2f(s1[1]));
            kh[3] = packh(ex2f(s1[2]), ex2f(s1[3]));

            int mp0 = 8 * kb + qc;
#pragma unroll
            for (int nb = 0; nb < 3; nb++) {
                int chx = 8 * nb + qr;
                uint32_t v0 = buf[1024 + mp0 * CHP + chx];
                uint32_t v1 = buf[1024 + (mp0 + 4) * CHP + chx];
                mma16(o[kb & 1][nb], kh, v0, v1);
            }
        }
    }

    // ---- combine p-halves ----
    float r[12];
#pragma unroll
    for (int nb = 0; nb < 3; nb++)
#pragma unroll
        for (int i = 0; i < 4; i++)
            r[nb * 4 + i] = o[0][nb][i] + o[1][nb][i];

    // ---- intra-CTA reduce across warp-groups (reuse sbuf as float scratch) ----
    float* red = (float*)&sbuf[0][0][0];   // 256*12 floats = 12 KB
    __syncthreads();                       // all smem panel reads done
    if (hw == 1) {
#pragma unroll
        for (int j = 0; j < 12; j++) red[wtid * 12 + j] = r[j];
    }
    __syncthreads();
    if (hw == 0) {
#pragma unroll
        for (int j = 0; j < 12; j++) r[j] += red[wtid * 12 + j];

        // writeback: rows (row, row+8), ch = 8nb + 2qc + {0,1}
        float* ob = out + (size_t)b * CH * NPTS + (size_t)nt * 128;
#pragma unroll
        for (int nb = 0; nb < 3; nb++) {
            int ch0 = 8 * nb + 2 * qc;
            if (ch0 < CH) {
                ob[(size_t)ch0 * NPTS + row]     = r[nb * 4 + 0];
                ob[(size_t)ch0 * NPTS + row + 8] = r[nb * 4 + 2];
            }
            if (ch0 + 1 < CH) {
                ob[(size_t)(ch0 + 1) * NPTS + row]     = r[nb * 4 + 1];
                ob[(size_t)(ch0 + 1) * NPTS + row + 8] = r[nb * 4 + 3];
            }
        }
    }
}

// ---------------------------------------------------------------------------
extern "C" void kernel_launch(void* const* d_in, const int* in_sizes, int n_in,
                              void* d_out, int out_size) {
    const float* cur_state = (const float*)d_in[0];   // [2,21,96,96]
    const float* img       = (const float*)d_in[1];   // [2,3,96,96]
    float* out             = (float*)d_out;           // [2,21,96,96]

    prep_all<<<(NV + 255) / 256, 256>>>(cur_state, img);
    gauss_mma<<<dim3(NT, BATCH), TPB>>>(out);
}